// round 15
// baseline (speedup 1.0000x reference)
#include <cuda_runtime.h>

#define T_STEPS 64
#define BATCH   32768
#define NCBLK   256
#define BLK     128
#define CHUNK   8
#define SEG     4
#define FULLM   0xffffffffu

// Raw per-step coefficients: [t][p][w] float2 (p=row-pair, w=0..15):
//   w0-5: M pairs, w6-11: N pairs, w12-14: K pairs, w15: pad(0)
__device__ __align__(16) float2 g_coef2[T_STEPS * 48];
__device__ int g_flag;

__global__ void reset_kernel() { g_flag = 0; }

// Composite smem layout per segment (COMP_PAIRS float2):
//  mblk  [j*18 + p*6 + c]          : pair (Mc_j[2p][c], Mc_j[2p+1][c])     (72 pairs)
//  ublk  [72 + tri(i,j)*30 + p*10 + c] : c<6 -> Ntilde_{j,i} col c; c=6..8 -> Ktilde col c-6; c=9 pad
#define MBLK_PAIRS 72
#define COMP_PAIRS 372

// ---------------- f32x2 helpers ----------------
__device__ __forceinline__ unsigned long long pack2(float lo, float hi) {
    unsigned long long r;
    asm("mov.b64 %0, {%1, %2};" : "=l"(r) : "f"(lo), "f"(hi));
    return r;
}
__device__ __forceinline__ void unpack2(float& lo, float& hi, unsigned long long v) {
    asm("mov.b64 {%0, %1}, %2;" : "=f"(lo), "=f"(hi) : "l"(v));
}
__device__ __forceinline__ unsigned long long fma2(unsigned long long a,
                                                   unsigned long long b,
                                                   unsigned long long c) {
    unsigned long long d;
    asm("fma.rn.f32x2 %0, %1, %2, %3;" : "=l"(d) : "l"(a), "l"(b), "l"(c));
    return d;
}
__device__ __forceinline__ unsigned long long add2(unsigned long long a,
                                                   unsigned long long b) {
    unsigned long long d;
    asm("add.rn.f32x2 %0, %1, %2;" : "=l"(d) : "l"(a), "l"(b));
    return d;
}

__global__ void __launch_bounds__(BLK)
fused_kernel(const float* __restrict__ meas,
             const float* __restrict__ useq,
             const float* __restrict__ mean0,
             const float* __restrict__ cov0,
             const float* __restrict__ gA,
             const float* __restrict__ gBm,
             const float* __restrict__ gQt,
             const float* __restrict__ gC,
             const float* __restrict__ gRt,
             float* __restrict__ out)
{
    __shared__ float sA[36], sC[18], sAP[36], sCP[18];
    __shared__ __align__(16) float2 sraw[CHUNK * 48];      // 3 KB raw chunk
    __shared__ __align__(16) float2 scomp[2 * COMP_PAIRS]; // 6 KB composites (2 segments)

    if (blockIdx.x == 0) {
        // ================= PRODUCER: spill-free smem-transpose Riccati (unchanged) ====
        if (threadIdx.x >= 32) return;
        const int lane = threadIdx.x;
        const int jc = lane < 6 ? lane : 5;

        for (int e = lane; e < 36; e += 32) sA[e] = gA[e];
        for (int e = lane; e < 18; e += 32) sC[e] = gC[e];
        __syncwarp();

        float Acol[6], Bmcol[6], Qcol[6], Pcol[6];
        #pragma unroll
        for (int i = 0; i < 6; i++) {
            Acol[i]  = __ldg(&gA[i*6 + jc]);
            Bmcol[i] = __ldg(&gBm[i*6 + jc]);
            Pcol[i]  = __ldg(&cov0[i*6 + jc]);       // cov0 batch-uniform
            float acc = 0.f;
            #pragma unroll
            for (int k = 0; k < 6; k++) acc += __ldg(&gQt[i*6+k]) * __ldg(&gQt[jc*6+k]);
            Qcol[i] = acc;
        }
        float r00 = 0.f, r01 = 0.f, r02 = 0.f, r11 = 0.f, r12 = 0.f, r22 = 0.f;
        #pragma unroll
        for (int k = 0; k < 3; k++) {
            float a0 = __ldg(&gRt[0*3+k]), a1 = __ldg(&gRt[1*3+k]), a2 = __ldg(&gRt[2*3+k]);
            r00 += a0*a0; r01 += a0*a1; r02 += a0*a2;
            r11 += a1*a1; r12 += a1*a2; r22 += a2*a2;
        }
        float CAcol[3], CBcol[3];
        #pragma unroll
        for (int b = 0; b < 3; b++) {
            float ca = 0.f, cb = 0.f;
            #pragma unroll
            for (int k = 0; k < 6; k++) { ca += sC[b*6+k] * Acol[k]; cb += sC[b*6+k] * Bmcol[k]; }
            CAcol[b] = ca; CBcol[b] = cb;
        }

        for (int t = 0; t < T_STEPS; t++) {
            float AP[6];
            #pragma unroll
            for (int i = 0; i < 6; i++) {
                float acc = 0.f;
                #pragma unroll
                for (int k = 0; k < 6; k++) acc += sA[i*6+k] * Pcol[k];
                AP[i] = acc;
            }
            if (lane < 6) {
                #pragma unroll
                for (int i = 0; i < 6; i++) sAP[i*6 + lane] = AP[i];
            }
            __syncwarp();
            float APr[6];
            #pragma unroll
            for (int k = 0; k < 6; k++) APr[k] = sAP[jc*6 + k];
            float Pp[6];
            #pragma unroll
            for (int c = 0; c < 6; c++) {
                float acc = Qcol[c];
                #pragma unroll
                for (int k = 0; k < 6; k++) acc += APr[k] * sA[c*6+k];
                Pp[c] = acc;
            }
            float CPc[3];
            #pragma unroll
            for (int a = 0; a < 3; a++) {
                float acc = 0.f;
                #pragma unroll
                for (int k = 0; k < 6; k++) acc += sC[a*6+k] * Pp[k];
                CPc[a] = acc;
            }
            if (lane < 6) {
                #pragma unroll
                for (int a = 0; a < 3; a++) sCP[a*6 + lane] = CPc[a];
            }
            __syncwarp();
            float CPall[3][6];
            #pragma unroll
            for (int b = 0; b < 3; b++)
                #pragma unroll
                for (int k = 0; k < 6; k++)
                    CPall[b][k] = sCP[b*6 + k];
            float s00 = r00, s01 = r01, s02 = r02, s11 = r11, s12 = r12, s22 = r22;
            #pragma unroll
            for (int k = 0; k < 6; k++) {
                float c0 = sC[k], c1 = sC[6+k], c2 = sC[12+k];
                s00 += c0 * CPall[0][k]; s01 += c0 * CPall[1][k]; s02 += c0 * CPall[2][k];
                s11 += c1 * CPall[1][k]; s12 += c1 * CPall[2][k]; s22 += c2 * CPall[2][k];
            }
            float i00 = s11*s22 - s12*s12;
            float i01 = s02*s12 - s01*s22;
            float i02 = s01*s12 - s02*s11;
            float i11 = s00*s22 - s02*s02;
            float i12 = s01*s02 - s00*s12;
            float i22 = s00*s11 - s01*s01;
            float rdet = 1.0f / (s00*i00 + s01*i01 + s02*i02);
            i00 *= rdet; i01 *= rdet; i02 *= rdet;
            i11 *= rdet; i12 *= rdet; i22 *= rdet;
            float g0 = i00*CAcol[0] + i01*CAcol[1] + i02*CAcol[2];
            float g1 = i01*CAcol[0] + i11*CAcol[1] + i12*CAcol[2];
            float g2 = i02*CAcol[0] + i12*CAcol[1] + i22*CAcol[2];
            float h0 = i00*CBcol[0] + i01*CBcol[1] + i02*CBcol[2];
            float h1 = i01*CBcol[0] + i11*CBcol[1] + i12*CBcol[2];
            float h2 = i02*CBcol[0] + i12*CBcol[1] + i22*CBcol[2];
            float p0 = i00*CPc[0] + i01*CPc[1] + i02*CPc[2];
            float p1 = i01*CPc[0] + i11*CPc[1] + i12*CPc[2];
            float p2 = i02*CPc[0] + i12*CPc[1] + i22*CPc[2];
            float sv0 = (jc == 0) ? i00 : (jc == 1) ? i01 : i02;
            float sv1 = (jc == 0) ? i01 : (jc == 1) ? i11 : i12;
            float sv2 = (jc == 0) ? i02 : (jc == 1) ? i12 : i22;
            float Mv[6], Nv[6], Kv[6];
            #pragma unroll
            for (int i = 0; i < 6; i++) {
                float c0 = CPall[0][i], c1 = CPall[1][i], c2 = CPall[2][i];
                Mv[i]   = Acol[i]  - (c0*g0 + c1*g1 + c2*g2);
                Nv[i]   = Bmcol[i] - (c0*h0 + c1*h1 + c2*h2);
                Pcol[i] = Pp[i]    - (c0*p0 + c1*p1 + c2*p2);
                Kv[i]   = c0*sv0 + c1*sv1 + c2*sv2;
            }
            if (lane < 6) {
                float2* g = g_coef2 + t * 48;
                #pragma unroll
                for (int p = 0; p < 3; p++) {
                    g[p*16 + lane]     = make_float2(Mv[2*p], Mv[2*p+1]);
                    g[p*16 + 6 + lane] = make_float2(Nv[2*p], Nv[2*p+1]);
                }
                if (lane < 3) {
                    #pragma unroll
                    for (int p = 0; p < 3; p++)
                        g[p*16 + 12 + lane] = make_float2(Kv[2*p], Kv[2*p+1]);
                } else {
                    g[(lane - 3)*16 + 15] = make_float2(0.f, 0.f);
                }
            }
            if ((t & (CHUNK - 1)) == CHUNK - 1) {
                __threadfence();
                __syncwarp();
                if (lane == 0) atomicExch(&g_flag, t + 1);
            }
        }
    } else {
        // ================= CONSUMERS: segment-composite mean recursion =================
        const int tid = threadIdx.x;
        const int b = (blockIdx.x - 1) * BLK + tid;

        unsigned long long md[6];
        {
            const float2* mp = reinterpret_cast<const float2*>(mean0 + (size_t)b * 6);
            float2 a = mp[0], c = mp[1], d = mp[2];
            md[0] = pack2(a.x, a.x); md[1] = pack2(a.y, a.y);
            md[2] = pack2(c.x, c.x); md[3] = pack2(c.y, c.y);
            md[4] = pack2(d.x, d.x); md[5] = pack2(d.y, d.y);
        }
        const float* zbase = meas + (size_t)b * 3;
        const float* ubase = useq + (size_t)b * 6;
        float*       obase = out  + (size_t)b * 6;

        #pragma unroll 1
        for (int c = 0; c < T_STEPS / CHUNK; c++) {
            const int target = (c + 1) * CHUNK;
            if (tid == 0) {
                while (((volatile int*)&g_flag)[0] < target) { }
            }
            __syncthreads();
            __threadfence();   // acquire for the __ldcg staging below
            // ---- stage raw chunk (192 float4) ----
            {
                const float4* src = reinterpret_cast<const float4*>(g_coef2 + (size_t)c * CHUNK * 48);
                float4* dst = reinterpret_cast<float4*>(sraw);
                #pragma unroll
                for (int e = tid; e < CHUNK * 24; e += BLK) dst[e] = __ldcg(src + e);
            }
            __syncthreads();

            // ---- build composites: copies (level 0 + diagonal) ----
            for (int it = tid; it < 2 * 18; it += BLK) {             // Mc_0 = M_0
                int seg = it / 18, r = it % 18, p = r / 6, cc = r % 6;
                scomp[seg*COMP_PAIRS + p*6 + cc] = sraw[(seg*SEG)*48 + p*16 + cc];
            }
            for (int it = tid; it < 216; it += BLK) {                // ublk[j][j] = N_j|K_j
                int seg = it / 108, r = it % 108;
                int j = r / 27, rr = r % 27, p = rr / 9, cc = rr % 9;
                int st = seg*SEG + j;
                float2 v = (cc < 6) ? sraw[st*48 + p*16 + 6 + cc]
                                    : sraw[st*48 + p*16 + 12 + (cc - 6)];
                int tri = j*(j+1)/2 + j;
                scomp[seg*COMP_PAIRS + MBLK_PAIRS + tri*30 + p*10 + cc] = v;
            }
            __syncthreads();
            // ---- levels j = 1..3: left-multiply everything by M_j ----
            for (int j = 1; j < 4; j++) {
                const int per_seg = 18 + 27 * j;
                for (int it = tid; it < 2 * per_seg; it += BLK) {
                    int seg = it / per_seg, r = it % per_seg;
                    const float2* Mj = &sraw[(seg*SEG + j)*48];
                    float2* base = &scomp[seg*COMP_PAIRS];
                    int p, cc, strideQ;
                    const float2* oldcol;
                    float2* dst;
                    if (r < 18) {
                        p = r / 6; cc = r % 6;
                        oldcol = base + (j-1)*18 + cc; strideQ = 6;
                        dst = base + j*18 + p*6 + cc;
                    } else {
                        int r2 = r - 18;
                        int i = r2 / 27, rr = r2 % 27;
                        p = rr / 9; cc = rr % 9;
                        int triOld = (j-1)*j/2 + i;
                        int triNew = j*(j+1)/2 + i;
                        oldcol = base + MBLK_PAIRS + triOld*30 + cc; strideQ = 10;
                        dst = base + MBLK_PAIRS + triNew*30 + p*10 + cc;
                    }
                    float old[6];
                    #pragma unroll
                    for (int q = 0; q < 3; q++) {
                        float2 ov = oldcol[q*strideQ];
                        old[2*q] = ov.x; old[2*q+1] = ov.y;
                    }
                    float nx = 0.f, ny = 0.f;
                    #pragma unroll
                    for (int k = 0; k < 6; k++) {
                        float2 mp = Mj[p*16 + k];
                        nx += mp.x * old[k];
                        ny += mp.y * old[k];
                    }
                    *dst = make_float2(nx, ny);
                }
                __syncthreads();
            }

            // ---- evaluate 2 segments ----
            #pragma unroll
            for (int seg = 0; seg < 2; seg++) {
                const int t0 = c * CHUNK + seg * SEG;
                // batch-load segment inputs (MLP=20)
                float uz[4][9];
                #pragma unroll
                for (int s = 0; s < 4; s++) {
                    const float2* uq = reinterpret_cast<const float2*>(ubase + (size_t)(t0+s) * BATCH * 6);
                    float2 ua = uq[0], ub2 = uq[1], uc2 = uq[2];
                    uz[s][0]=ua.x; uz[s][1]=ua.y; uz[s][2]=ub2.x; uz[s][3]=ub2.y; uz[s][4]=uc2.x; uz[s][5]=uc2.y;
                    const float* zq = zbase + (size_t)(t0+s) * BATCH * 3;
                    uz[s][6]=zq[0]; uz[s][7]=zq[1]; uz[s][8]=zq[2];
                }
                const float2* cbp = scomp + seg * COMP_PAIRS;
                unsigned long long acc[4][3];
                // m contributions
                #pragma unroll
                for (int j = 0; j < 4; j++)
                    #pragma unroll
                    for (int p = 0; p < 3; p++) {
                        const ulonglong2* q = reinterpret_cast<const ulonglong2*>(cbp + j*18 + p*6);
                        ulonglong2 q0 = q[0], q1 = q[1], q2 = q[2];
                        unsigned long long a_ = fma2(q0.x, md[0], 0ull);
                        a_ = fma2(q0.y, md[1], a_);
                        a_ = fma2(q1.x, md[2], a_);
                        unsigned long long b_ = fma2(q1.y, md[3], 0ull);
                        b_ = fma2(q2.x, md[4], b_);
                        b_ = fma2(q2.y, md[5], b_);
                        acc[j][p] = add2(a_, b_);
                    }
                // u/z contributions (triangular)
                #pragma unroll
                for (int i = 0; i < 4; i++) {
                    unsigned long long uzp[9];
                    #pragma unroll
                    for (int e = 0; e < 9; e++) uzp[e] = pack2(uz[i][e], uz[i][e]);
                    #pragma unroll
                    for (int j = 0; j < 4; j++) {
                        if (j < i) continue;
                        const int tri = j*(j+1)/2 + i;
                        #pragma unroll
                        for (int p = 0; p < 3; p++) {
                            const ulonglong2* q =
                                reinterpret_cast<const ulonglong2*>(cbp + MBLK_PAIRS + tri*30 + p*10);
                            ulonglong2 q0 = q[0], q1 = q[1], q2 = q[2], q3 = q[3], q4 = q[4];
                            unsigned long long a_ = fma2(q0.x, uzp[0], acc[j][p]);
                            a_ = fma2(q0.y, uzp[1], a_);
                            a_ = fma2(q1.x, uzp[2], a_);
                            a_ = fma2(q1.y, uzp[3], a_);
                            a_ = fma2(q2.x, uzp[4], a_);
                            a_ = fma2(q2.y, uzp[5], a_);
                            a_ = fma2(q3.x, uzp[6], a_);
                            a_ = fma2(q3.y, uzp[7], a_);
                            acc[j][p] = fma2(q4.x, uzp[8], a_);
                        }
                    }
                }
                // store 4 outputs, advance m
                #pragma unroll
                for (int j = 0; j < 4; j++) {
                    unsigned long long* oq =
                        reinterpret_cast<unsigned long long*>(obase + (size_t)(t0+j) * BATCH * 6);
                    oq[0] = acc[j][0]; oq[1] = acc[j][1]; oq[2] = acc[j][2];
                }
                float lo, hi;
                unpack2(lo, hi, acc[3][0]); md[0] = pack2(lo, lo); md[1] = pack2(hi, hi);
                unpack2(lo, hi, acc[3][1]); md[2] = pack2(lo, lo); md[3] = pack2(hi, hi);
                unpack2(lo, hi, acc[3][2]); md[4] = pack2(lo, lo); md[5] = pack2(hi, hi);
            }
            __syncthreads();   // protect scomp/sraw reuse next chunk
        }
    }
}

extern "C" void kernel_launch(void* const* d_in, const int* in_sizes, int n_in,
                              void* d_out, int out_size)
{
    const float* meas  = (const float*)d_in[0];   // (T, B, O)
    const float* useq  = (const float*)d_in[1];   // (T, B, U)
    const float* mean0 = (const float*)d_in[2];   // (B, D)
    const float* cov0  = (const float*)d_in[3];   // (B, D, D) -- batch-uniform
    const float* A     = (const float*)d_in[4];   // (D, D)
    const float* Bm    = (const float*)d_in[5];   // (D, U)
    const float* Qt    = (const float*)d_in[6];   // (D, D) lower-tri
    const float* C     = (const float*)d_in[7];   // (O, D)
    const float* Rt    = (const float*)d_in[8];   // (O, O) lower-tri
    float* out = (float*)d_out;                   // (T, B, D)

    reset_kernel<<<1, 1>>>();
    fused_kernel<<<NCBLK + 1, BLK>>>(meas, useq, mean0, cov0, A, Bm, Qt, C, Rt, out);
}